// round 1
// baseline (speedup 1.0000x reference)
#include <cuda_runtime.h>

// ---------------------------------------------------------------------------
// GNN_node: 3-layer relational GIN.
//   h0 = sum_f emb[f, x[:,f], :]                       [N,128]
//   per layer l, per edge-set k:
//     z   = (1+eps_l)*h + scatter_add(h[src]->dst)     [N,128]
//     y1  = z @ W1_l + b1_l                            [N,256]
//     z2  = relu(BN(y1; g1,be1))       (batch stats)   [N,256]
//     msg_k = z2 @ W2_l + b2_l                         [N,128]
//   h = relu(BN(sum_k softmax(alpha_l)[k]*msg_k; bn_g, bn_b))
// ---------------------------------------------------------------------------

namespace {
constexpr int D     = 128;
constexpr int D2    = 256;
constexpr int NFEAT = 9;
constexpr int VOC   = 100;
constexpr int KS    = 3;
constexpr int LAY   = 3;
constexpr int NPAD  = 100096;   // 782 * 128, covers N = 100000
}

// Scratch (zero-initialized at module load; static device globals are the
// sanctioned scratch mechanism — no runtime allocation).
__device__ float g_h   [NPAD * D];
__device__ float g_agg [NPAD * D];
__device__ float g_y1  [NPAD * D2];
__device__ float g_hacc[NPAD * D];
__device__ float g_sum  [D2];
__device__ float g_sq   [D2];
__device__ float g_scale[D2];
__device__ float g_shift[D2];
__device__ float g_aw   [KS];

// ---------------------------------------------------------------------------
// AtomEncoder: one warp per node, float4 per lane (128 dims = 32 lanes x 4).
// ---------------------------------------------------------------------------
__global__ void embed_kernel(const int* __restrict__ x, const float* __restrict__ emb,
                             float* __restrict__ H, int N)
{
    int gt = blockIdx.x * blockDim.x + threadIdx.x;
    int node = gt >> 5, lane = gt & 31;
    if (node >= N) return;
    float4 acc = make_float4(0.f, 0.f, 0.f, 0.f);
#pragma unroll
    for (int f = 0; f < NFEAT; f++) {
        int idx = x[node * NFEAT + f];
        float4 v = ((const float4*)(emb + ((size_t)f * VOC + idx) * D))[lane];
        acc.x += v.x; acc.y += v.y; acc.z += v.z; acc.w += v.w;
    }
    ((float4*)(H + (size_t)node * D))[lane] = acc;
}

// softmax over the 3 relation weights for one layer
__global__ void softmax3_kernel(const float* __restrict__ alpha, float* __restrict__ a)
{
    float a0 = alpha[0], a1 = alpha[1], a2 = alpha[2];
    float m  = fmaxf(a0, fmaxf(a1, a2));
    float e0 = expf(a0 - m), e1 = expf(a1 - m), e2 = expf(a2 - m);
    float inv = 1.f / (e0 + e1 + e2);
    a[0] = e0 * inv; a[1] = e1 * inv; a[2] = e2 * inv;
}

// agg = (1 + eps_l) * h   (self term of GIN, before scatter adds neighbors)
__global__ void scale_copy_kernel(const float* __restrict__ H, float* __restrict__ Agg,
                                  const float* __restrict__ epsp, int n4)
{
    int i = blockIdx.x * blockDim.x + threadIdx.x;
    if (i >= n4) return;
    float s = 1.0f + epsp[0];
    float4 v = ((const float4*)H)[i];
    v.x *= s; v.y *= s; v.z *= s; v.w *= s;
    ((float4*)Agg)[i] = v;
}

// One warp per edge: coalesced 512B gather of h[src], vectorized v4 float
// reduction into agg[dst] (4x fewer L2 atomic ops than scalar atomicAdd).
__global__ void scatter_kernel(const float* __restrict__ H, const int* __restrict__ src,
                               const int* __restrict__ dst, float* __restrict__ Agg, int E)
{
    int gt = blockIdx.x * blockDim.x + threadIdx.x;
    int e = gt >> 5, lane = gt & 31;
    if (e >= E) return;
    int s = src[e], d = dst[e];
    float4 v = ((const float4*)(H + (size_t)s * D))[lane];
    float* p = Agg + (size_t)d * D + lane * 4;
    asm volatile("red.global.add.v4.f32 [%0], {%1, %2, %3, %4};"
                 :: "l"(p), "f"(v.x), "f"(v.y), "f"(v.z), "f"(v.w)
                 : "memory");
}

// ---------------------------------------------------------------------------
// SGEMM 1: C[M,256] = A[M,128] @ B[128,256] + bias
// 128x128 tiles, BK=16, 256 threads, 8x8 microtile, float4 loads.
// A rows are padded to NPAD (zeros), so A loads are unpredicated.
// ---------------------------------------------------------------------------
__global__ __launch_bounds__(256) void gemm1_kernel(
    const float* __restrict__ A, const float* __restrict__ B,
    const float* __restrict__ bias, float* __restrict__ C, int M)
{
    __shared__ float As[16][128];
    __shared__ float Bs[16][128];
    const int tid = threadIdx.x;
    const int rowBase = blockIdx.x * 128;
    const int colBase = blockIdx.y * 128;
    const int tx = tid & 15;
    const int ty = tid >> 4;
    const int arow = tid >> 2;
    const int acol = (tid & 3) << 2;
    const int brow = tid >> 5;
    const int bcol = (tid & 31) << 2;

    float acc[8][8];
#pragma unroll
    for (int i = 0; i < 8; i++)
#pragma unroll
        for (int j = 0; j < 8; j++) acc[i][j] = 0.f;

    for (int kk = 0; kk < 128; kk += 16) {
#pragma unroll
        for (int it = 0; it < 2; it++) {
            int r = arow + it * 64;
            float4 v = *(const float4*)(A + (size_t)(rowBase + r) * D + kk + acol);
            As[acol + 0][r] = v.x;
            As[acol + 1][r] = v.y;
            As[acol + 2][r] = v.z;
            As[acol + 3][r] = v.w;
        }
#pragma unroll
        for (int it = 0; it < 2; it++) {
            int r = brow + it * 8;
            *(float4*)&Bs[r][bcol] =
                *(const float4*)(B + (size_t)(kk + r) * D2 + colBase + bcol);
        }
        __syncthreads();
#pragma unroll
        for (int k = 0; k < 16; k++) {
            float4 a0 = *(const float4*)&As[k][ty * 8];
            float4 a1 = *(const float4*)&As[k][ty * 8 + 4];
            float4 b0 = *(const float4*)&Bs[k][tx * 8];
            float4 b1 = *(const float4*)&Bs[k][tx * 8 + 4];
            float ra[8] = {a0.x, a0.y, a0.z, a0.w, a1.x, a1.y, a1.z, a1.w};
            float rb[8] = {b0.x, b0.y, b0.z, b0.w, b1.x, b1.y, b1.z, b1.w};
#pragma unroll
            for (int i = 0; i < 8; i++)
#pragma unroll
                for (int j = 0; j < 8; j++)
                    acc[i][j] = fmaf(ra[i], rb[j], acc[i][j]);
        }
        __syncthreads();
    }
#pragma unroll
    for (int i = 0; i < 8; i++) {
        int r = rowBase + ty * 8 + i;
        if (r < M) {
#pragma unroll
            for (int jj = 0; jj < 2; jj++) {
                int c = colBase + tx * 8 + jj * 4;
                float4 o;
                o.x = acc[i][jj * 4 + 0] + bias[c + 0];
                o.y = acc[i][jj * 4 + 1] + bias[c + 1];
                o.z = acc[i][jj * 4 + 2] + bias[c + 2];
                o.w = acc[i][jj * 4 + 3] + bias[c + 3];
                *(float4*)(C + (size_t)r * D2 + c) = o;
            }
        }
    }
}

// ---------------------------------------------------------------------------
// SGEMM 2 (fused BN+ReLU on A-load, weighted accumulate epilogue):
//   Out (+)= a[k] * ( relu(A*scale+shift) @ B[256,128] + bias )
// ---------------------------------------------------------------------------
__global__ __launch_bounds__(256) void gemm2_kernel(
    const float* __restrict__ A, const float* __restrict__ B,
    const float* __restrict__ bias,
    const float* __restrict__ scale, const float* __restrict__ shift,
    const float* __restrict__ aw, int kidx,
    float* __restrict__ Out, int M)
{
    __shared__ float As[16][128];
    __shared__ float Bs[16][128];
    __shared__ float sSc[256], sSh[256];
    const int tid = threadIdx.x;
    sSc[tid] = scale[tid];
    sSh[tid] = shift[tid];
    const int rowBase = blockIdx.x * 128;
    const int tx = tid & 15;
    const int ty = tid >> 4;
    const int arow = tid >> 2;
    const int acol = (tid & 3) << 2;
    const int brow = tid >> 5;
    const int bcol = (tid & 31) << 2;

    float acc[8][8];
#pragma unroll
    for (int i = 0; i < 8; i++)
#pragma unroll
        for (int j = 0; j < 8; j++) acc[i][j] = 0.f;

    __syncthreads();

    for (int kk = 0; kk < 256; kk += 16) {
#pragma unroll
        for (int it = 0; it < 2; it++) {
            int r = arow + it * 64;
            float4 v = *(const float4*)(A + (size_t)(rowBase + r) * D2 + kk + acol);
            int c = kk + acol;
            v.x = fmaxf(fmaf(v.x, sSc[c + 0], sSh[c + 0]), 0.f);
            v.y = fmaxf(fmaf(v.y, sSc[c + 1], sSh[c + 1]), 0.f);
            v.z = fmaxf(fmaf(v.z, sSc[c + 2], sSh[c + 2]), 0.f);
            v.w = fmaxf(fmaf(v.w, sSc[c + 3], sSh[c + 3]), 0.f);
            As[acol + 0][r] = v.x;
            As[acol + 1][r] = v.y;
            As[acol + 2][r] = v.z;
            As[acol + 3][r] = v.w;
        }
#pragma unroll
        for (int it = 0; it < 2; it++) {
            int r = brow + it * 8;
            *(float4*)&Bs[r][bcol] = *(const float4*)(B + (size_t)(kk + r) * D + bcol);
        }
        __syncthreads();
#pragma unroll
        for (int k = 0; k < 16; k++) {
            float4 a0 = *(const float4*)&As[k][ty * 8];
            float4 a1 = *(const float4*)&As[k][ty * 8 + 4];
            float4 b0 = *(const float4*)&Bs[k][tx * 8];
            float4 b1 = *(const float4*)&Bs[k][tx * 8 + 4];
            float ra[8] = {a0.x, a0.y, a0.z, a0.w, a1.x, a1.y, a1.z, a1.w};
            float rb[8] = {b0.x, b0.y, b0.z, b0.w, b1.x, b1.y, b1.z, b1.w};
#pragma unroll
            for (int i = 0; i < 8; i++)
#pragma unroll
                for (int j = 0; j < 8; j++)
                    acc[i][j] = fmaf(ra[i], rb[j], acc[i][j]);
        }
        __syncthreads();
    }

    float ak = aw[kidx];
#pragma unroll
    for (int i = 0; i < 8; i++) {
        int r = rowBase + ty * 8 + i;
        if (r < M) {
#pragma unroll
            for (int jj = 0; jj < 2; jj++) {
                int c = tx * 8 + jj * 4;
                float4 o;
                o.x = (acc[i][jj * 4 + 0] + bias[c + 0]) * ak;
                o.y = (acc[i][jj * 4 + 1] + bias[c + 1]) * ak;
                o.z = (acc[i][jj * 4 + 2] + bias[c + 2]) * ak;
                o.w = (acc[i][jj * 4 + 3] + bias[c + 3]) * ak;
                float4* dp = (float4*)(Out + (size_t)r * D + c);
                if (kidx != 0) {
                    float4 old = *dp;
                    o.x += old.x; o.y += old.y; o.z += old.z; o.w += old.w;
                }
                *dp = o;
            }
        }
    }
}

// ---------------------------------------------------------------------------
// BatchNorm statistics: column sums and sum-of-squares (blockDim.x == C)
// ---------------------------------------------------------------------------
__global__ void zero_stats_kernel(float* __restrict__ s, float* __restrict__ q)
{
    int i = threadIdx.x;
    s[i] = 0.f;
    q[i] = 0.f;
}

__global__ void colstats_kernel(const float* __restrict__ X, int M, int C,
                                float* __restrict__ s, float* __restrict__ q)
{
    int c = threadIdx.x;
    float ps = 0.f, pq = 0.f;
    for (int r = blockIdx.x; r < M; r += gridDim.x) {
        float v = X[(size_t)r * C + c];
        ps += v;
        pq += v * v;
    }
    atomicAdd(&s[c], ps);
    atomicAdd(&q[c], pq);
}

// mean/var -> affine (scale, shift) so BN+affine is a single FMA downstream
__global__ void finalize_kernel(const float* __restrict__ s, const float* __restrict__ q,
                                const float* __restrict__ g, const float* __restrict__ b,
                                float* __restrict__ scale, float* __restrict__ shift,
                                float invN)
{
    int c = threadIdx.x;
    float mu   = s[c] * invN;
    float var  = q[c] * invN - mu * mu;
    float rstd = rsqrtf(var + 1e-5f);
    float sc   = rstd * g[c];
    scale[c] = sc;
    shift[c] = b[c] - mu * sc;
}

__global__ void bnrelu_kernel(const float* __restrict__ X, const float* __restrict__ scale,
                              const float* __restrict__ shift, float* __restrict__ Out, int n4)
{
    int i = blockIdx.x * blockDim.x + threadIdx.x;
    if (i >= n4) return;
    int c4 = i & 31;   // 128 floats per row = 32 float4
    float4 v  = ((const float4*)X)[i];
    float4 sc = ((const float4*)scale)[c4];
    float4 sh = ((const float4*)shift)[c4];
    v.x = fmaxf(fmaf(v.x, sc.x, sh.x), 0.f);
    v.y = fmaxf(fmaf(v.y, sc.y, sh.y), 0.f);
    v.z = fmaxf(fmaf(v.z, sc.z, sh.z), 0.f);
    v.w = fmaxf(fmaf(v.w, sc.w, sh.w), 0.f);
    ((float4*)Out)[i] = v;
}

// ---------------------------------------------------------------------------

extern "C" void kernel_launch(void* const* d_in, const int* in_sizes, int n_in,
                              void* d_out, int out_size)
{
    const int*   x     = (const int*)  d_in[0];
    const int*   ke    = (const int*)  d_in[1];
    const float* emb   = (const float*)d_in[2];
    const float* W1    = (const float*)d_in[3];
    const float* b1    = (const float*)d_in[4];
    const float* g1    = (const float*)d_in[5];
    const float* be1   = (const float*)d_in[6];
    const float* W2    = (const float*)d_in[7];
    const float* b2    = (const float*)d_in[8];
    const float* eps   = (const float*)d_in[9];
    const float* alpha = (const float*)d_in[10];
    const float* bn_g  = (const float*)d_in[11];
    const float* bn_b  = (const float*)d_in[12];

    const int N = in_sizes[0] / NFEAT;
    const int E = in_sizes[1] / (KS * 2);
    const int n4 = N * (D / 4);
    const int nTilesM = (N + 127) / 128;

    float *p_h, *p_agg, *p_y1, *p_hacc, *p_sum, *p_sq, *p_scale, *p_shift, *p_aw;
    cudaGetSymbolAddress((void**)&p_h,     g_h);
    cudaGetSymbolAddress((void**)&p_agg,   g_agg);
    cudaGetSymbolAddress((void**)&p_y1,    g_y1);
    cudaGetSymbolAddress((void**)&p_hacc,  g_hacc);
    cudaGetSymbolAddress((void**)&p_sum,   g_sum);
    cudaGetSymbolAddress((void**)&p_sq,    g_sq);
    cudaGetSymbolAddress((void**)&p_scale, g_scale);
    cudaGetSymbolAddress((void**)&p_shift, g_shift);
    cudaGetSymbolAddress((void**)&p_aw,    g_aw);

    const float invN = 1.0f / (float)N;

    embed_kernel<<<(N * 32 + 255) / 256, 256>>>(x, emb, p_h, N);

    for (int l = 0; l < LAY; l++) {
        softmax3_kernel<<<1, 1>>>(alpha + l * KS, p_aw);

        for (int k = 0; k < KS; k++) {
            scale_copy_kernel<<<(n4 + 255) / 256, 256>>>(p_h, p_agg, eps + l, n4);
            scatter_kernel<<<(E * 32 + 255) / 256, 256>>>(
                p_h, ke + (size_t)(k * 2) * E, ke + (size_t)(k * 2 + 1) * E, p_agg, E);

            gemm1_kernel<<<dim3(nTilesM, 2), 256>>>(
                p_agg, W1 + (size_t)l * D * D2, b1 + l * D2, p_y1, N);

            zero_stats_kernel<<<1, D2>>>(p_sum, p_sq);
            colstats_kernel<<<2048, D2>>>(p_y1, N, D2, p_sum, p_sq);
            finalize_kernel<<<1, D2>>>(p_sum, p_sq, g1 + l * D2, be1 + l * D2,
                                       p_scale, p_shift, invN);

            gemm2_kernel<<<nTilesM, 256>>>(
                p_y1, W2 + (size_t)l * D2 * D, b2 + l * D,
                p_scale, p_shift, p_aw, k, p_hacc, N);
        }

        zero_stats_kernel<<<1, D>>>(p_sum, p_sq);
        colstats_kernel<<<2048, D>>>(p_hacc, N, D, p_sum, p_sq);
        finalize_kernel<<<1, D>>>(p_sum, p_sq, bn_g + l * D, bn_b + l * D,
                                  p_scale, p_shift, invN);

        float* outp = (l == LAY - 1) ? (float*)d_out : p_h;
        bnrelu_kernel<<<(n4 + 255) / 256, 256>>>(p_hacc, p_scale, p_shift, outp, n4);
    }
}

// round 3
// speedup vs baseline: 1.6351x; 1.6351x over previous
#include <cuda_runtime.h>
#include <cuda_bf16.h>
#include <cstdint>

// ---------------------------------------------------------------------------
// GNN_node: 3-layer relational GIN. Round 3: GEMMs on tensor cores via
// split-bf16 (bf16x3) mma.sync.m16n8k16 — ~1e-5 relative error, 3x bf16 work
// but ~10x faster than the scalar-FMA fp32 path.
// ---------------------------------------------------------------------------

namespace {
constexpr int D     = 128;
constexpr int D2    = 256;
constexpr int NFEAT = 9;
constexpr int VOC   = 100;
constexpr int KS    = 3;
constexpr int LAY   = 3;
constexpr int NPAD  = 100096;   // 782 * 128, covers N = 100000

constexpr int BM = 128, BN = 128, BK = 32;
}

// Scratch (zero-initialized at module load).
__device__ float g_h   [NPAD * D];
__device__ float g_agg [NPAD * D];
__device__ float g_y1  [NPAD * D2];
__device__ float g_hacc[NPAD * D];
__device__ float g_sum  [D2];
__device__ float g_sq   [D2];
__device__ float g_scale[D2];
__device__ float g_shift[D2];
__device__ float g_aw   [KS];
// pre-split weight planes (hi/lo bf16)
__device__ __align__(16) __nv_bfloat16 g_W1h[LAY * D * D2];
__device__ __align__(16) __nv_bfloat16 g_W1l[LAY * D * D2];
__device__ __align__(16) __nv_bfloat16 g_W2h[LAY * D2 * D];
__device__ __align__(16) __nv_bfloat16 g_W2l[LAY * D2 * D];

// ---------------------------------------------------------------------------
// PTX helpers
// ---------------------------------------------------------------------------
__device__ __forceinline__ void ldsm_x4(uint32_t r[4], uint32_t addr)
{
    asm volatile("ldmatrix.sync.aligned.m8n8.x4.shared.b16 {%0,%1,%2,%3}, [%4];"
                 : "=r"(r[0]), "=r"(r[1]), "=r"(r[2]), "=r"(r[3]) : "r"(addr));
}
__device__ __forceinline__ void ldsm_x4t(uint32_t r[4], uint32_t addr)
{
    asm volatile("ldmatrix.sync.aligned.m8n8.x4.trans.shared.b16 {%0,%1,%2,%3}, [%4];"
                 : "=r"(r[0]), "=r"(r[1]), "=r"(r[2]), "=r"(r[3]) : "r"(addr));
}
__device__ __forceinline__ void mma16816(float c[4], const uint32_t a[4], const uint32_t* b)
{
    asm volatile("mma.sync.aligned.m16n8k16.row.col.f32.bf16.bf16.f32 "
                 "{%0,%1,%2,%3},{%4,%5,%6,%7},{%8,%9},{%0,%1,%2,%3};"
                 : "+f"(c[0]), "+f"(c[1]), "+f"(c[2]), "+f"(c[3])
                 : "r"(a[0]), "r"(a[1]), "r"(a[2]), "r"(a[3]), "r"(b[0]), "r"(b[1]));
}
__device__ __forceinline__ uint32_t smem_u32(const void* p)
{
    return (uint32_t)__cvta_generic_to_shared(p);
}

// ---------------------------------------------------------------------------
// AtomEncoder: one warp per node, float4 per lane.
// ---------------------------------------------------------------------------
__global__ void embed_kernel(const int* __restrict__ x, const float* __restrict__ emb,
                             float* __restrict__ H, int N)
{
    int gt = blockIdx.x * blockDim.x + threadIdx.x;
    int node = gt >> 5, lane = gt & 31;
    if (node >= N) return;
    float4 acc = make_float4(0.f, 0.f, 0.f, 0.f);
#pragma unroll
    for (int f = 0; f < NFEAT; f++) {
        int idx = x[node * NFEAT + f];
        float4 v = ((const float4*)(emb + ((size_t)f * VOC + idx) * D))[lane];
        acc.x += v.x; acc.y += v.y; acc.z += v.z; acc.w += v.w;
    }
    ((float4*)(H + (size_t)node * D))[lane] = acc;
}

__global__ void softmax3_kernel(const float* __restrict__ alpha, float* __restrict__ a)
{
    float a0 = alpha[0], a1 = alpha[1], a2 = alpha[2];
    float m  = fmaxf(a0, fmaxf(a1, a2));
    float e0 = expf(a0 - m), e1 = expf(a1 - m), e2 = expf(a2 - m);
    float inv = 1.f / (e0 + e1 + e2);
    a[0] = e0 * inv; a[1] = e1 * inv; a[2] = e2 * inv;
}

// split all weight matrices into hi/lo bf16 planes (once per launch)
__global__ void wsplit_kernel(const float* __restrict__ W1, const float* __restrict__ W2,
                              __nv_bfloat16* __restrict__ w1h, __nv_bfloat16* __restrict__ w1l,
                              __nv_bfloat16* __restrict__ w2h, __nv_bfloat16* __restrict__ w2l)
{
    int i = blockIdx.x * blockDim.x + threadIdx.x;
    const int tot = LAY * D * D2;
    if (i < tot) {
        float v = W1[i];
        __nv_bfloat16 h = __float2bfloat16(v);
        w1h[i] = h;
        w1l[i] = __float2bfloat16(v - __bfloat162float(h));
    } else if (i < 2 * tot) {
        int j = i - tot;
        float v = W2[j];
        __nv_bfloat16 h = __float2bfloat16(v);
        w2h[j] = h;
        w2l[j] = __float2bfloat16(v - __bfloat162float(h));
    }
}

// agg = (1 + eps_l) * h
__global__ void scale_copy_kernel(const float* __restrict__ H, float* __restrict__ Agg,
                                  const float* __restrict__ epsp, int n4)
{
    int i = blockIdx.x * blockDim.x + threadIdx.x;
    if (i >= n4) return;
    float s = 1.0f + epsp[0];
    float4 v = ((const float4*)H)[i];
    v.x *= s; v.y *= s; v.z *= s; v.w *= s;
    ((float4*)Agg)[i] = v;
}

// One warp per edge: coalesced 512B gather, vectorized v4 reduction.
__global__ void scatter_kernel(const float* __restrict__ H, const int* __restrict__ src,
                               const int* __restrict__ dst, float* __restrict__ Agg, int E)
{
    int gt = blockIdx.x * blockDim.x + threadIdx.x;
    int e = gt >> 5, lane = gt & 31;
    if (e >= E) return;
    int s = src[e], d = dst[e];
    float4 v = ((const float4*)(H + (size_t)s * D))[lane];
    float* p = Agg + (size_t)d * D + lane * 4;
    asm volatile("red.global.add.v4.f32 [%0], {%1, %2, %3, %4};"
                 :: "l"(p), "f"(v.x), "f"(v.y), "f"(v.z), "f"(v.w)
                 : "memory");
}

// ---------------------------------------------------------------------------
// Tensor-core split-bf16 GEMM:  C[M, NTOT-tile] = op(A)[M, KTOT] @ B + bias
//  - A fp32, split into hi/lo bf16 on smem store
//  - B pre-split bf16 planes (Bh, Bl), row-major [KTOT][NTOT]
//  - combos: Ah*Bh + Al*Bh + Ah*Bl  (Al*Bl dropped; ~1e-5 rel error)
//  FUSE: apply BN(scale,shift)+ReLU to A elements before split (gemm2 path)
//  WACC: epilogue Out (+)= aw[kidx] * (acc + bias)   (gemm2 path)
// ---------------------------------------------------------------------------
template <int KTOT, int NTOT, bool FUSE, bool WACC>
__global__ __launch_bounds__(256, 2) void tgemm_kernel(
    const float* __restrict__ A,
    const __nv_bfloat16* __restrict__ Bhp, const __nv_bfloat16* __restrict__ Blp,
    const float* __restrict__ bias,
    const float* __restrict__ scale, const float* __restrict__ shift,
    const float* __restrict__ aw, int kidx,
    float* __restrict__ C, int M)
{
    __shared__ __nv_bfloat16 sAh[BM][BK + 8];
    __shared__ __nv_bfloat16 sAl[BM][BK + 8];
    __shared__ __nv_bfloat16 sBh[BK][BN + 8];
    __shared__ __nv_bfloat16 sBl[BK][BN + 8];
    __shared__ float sSc[256], sSh[256];

    const int tid  = threadIdx.x;
    const int wid  = tid >> 5;
    const int lane = tid & 31;
    const int wm   = wid >> 1;     // 0..3  (32-row warp tile)
    const int wn   = wid & 1;      // 0..1  (64-col warp tile)
    const int rowBase = blockIdx.x * BM;
    const int colBase = blockIdx.y * BN;

    if (FUSE) {
        if (tid < KTOT) { sSc[tid] = scale[tid]; sSh[tid] = shift[tid]; }
    }

    float acc[2][8][4];
#pragma unroll
    for (int m = 0; m < 2; m++)
#pragma unroll
        for (int n = 0; n < 8; n++)
#pragma unroll
            for (int q = 0; q < 4; q++) acc[m][n][q] = 0.f;

    const int ar = tid >> 3;        // 0..31 (row within pass)
    const int acv = tid & 7;        // float4 column
    const int br = tid >> 4;        // 0..15
    const int bcv = tid & 15;       // uint4 column

    for (int kk = 0; kk < KTOT; kk += BK) {
        __syncthreads();            // also orders sSc init on first iter
        // ---- A tile: load fp32, (optional BN+ReLU), split hi/lo ----
#pragma unroll
        for (int p = 0; p < 4; p++) {
            int r = ar + p * 32;
            float4 v = *(const float4*)(A + (size_t)(rowBase + r) * KTOT + kk + acv * 4);
            if (FUSE) {
                int c = kk + acv * 4;
                v.x = fmaxf(fmaf(v.x, sSc[c + 0], sSh[c + 0]), 0.f);
                v.y = fmaxf(fmaf(v.y, sSc[c + 1], sSh[c + 1]), 0.f);
                v.z = fmaxf(fmaf(v.z, sSc[c + 2], sSh[c + 2]), 0.f);
                v.w = fmaxf(fmaf(v.w, sSc[c + 3], sSh[c + 3]), 0.f);
            }
            float vv[4] = {v.x, v.y, v.z, v.w};
#pragma unroll
            for (int j = 0; j < 4; j += 2) {
                __nv_bfloat16 h0 = __float2bfloat16(vv[j]);
                __nv_bfloat16 h1 = __float2bfloat16(vv[j + 1]);
                __nv_bfloat16 l0 = __float2bfloat16(vv[j]     - __bfloat162float(h0));
                __nv_bfloat16 l1 = __float2bfloat16(vv[j + 1] - __bfloat162float(h1));
                __nv_bfloat162 th; th.x = h0; th.y = h1;
                __nv_bfloat162 tl; tl.x = l0; tl.y = l1;
                *(__nv_bfloat162*)&sAh[r][acv * 4 + j] = th;
                *(__nv_bfloat162*)&sAl[r][acv * 4 + j] = tl;
            }
        }
        // ---- B tile: copy bf16 planes ----
#pragma unroll
        for (int p = 0; p < 2; p++) {
            int r = br + p * 16;
            *(uint4*)&sBh[r][bcv * 8] =
                *(const uint4*)(Bhp + (size_t)(kk + r) * NTOT + colBase + bcv * 8);
            *(uint4*)&sBl[r][bcv * 8] =
                *(const uint4*)(Blp + (size_t)(kk + r) * NTOT + colBase + bcv * 8);
        }
        __syncthreads();

        // ---- MMA ----
#pragma unroll
        for (int kb = 0; kb < BK / 16; kb++) {
            uint32_t ah[2][4], al[2][4], bf[8][2];
#pragma unroll
            for (int m = 0; m < 2; m++) {
                int row = wm * 32 + m * 16 + (lane & 15);
                int col = kb * 16 + (lane >> 4) * 8;
                ldsm_x4(ah[m], smem_u32(&sAh[row][col]));
                ldsm_x4(al[m], smem_u32(&sAl[row][col]));
            }
            // plane Bh: combos Ah*Bh, Al*Bh
#pragma unroll
            for (int nb = 0; nb < 4; nb++) {
                int row = kb * 16 + (lane & 15);
                int col = wn * 64 + nb * 16 + (lane >> 4) * 8;
                uint32_t t[4];
                ldsm_x4t(t, smem_u32(&sBh[row][col]));
                bf[nb * 2][0] = t[0]; bf[nb * 2][1] = t[1];
                bf[nb * 2 + 1][0] = t[2]; bf[nb * 2 + 1][1] = t[3];
            }
#pragma unroll
            for (int m = 0; m < 2; m++)
#pragma unroll
                for (int n = 0; n < 8; n++) {
                    mma16816(acc[m][n], ah[m], bf[n]);
                    mma16816(acc[m][n], al[m], bf[n]);
                }
            // plane Bl: combo Ah*Bl
#pragma unroll
            for (int nb = 0; nb < 4; nb++) {
                int row = kb * 16 + (lane & 15);
                int col = wn * 64 + nb * 16 + (lane >> 4) * 8;
                uint32_t t[4];
                ldsm_x4t(t, smem_u32(&sBl[row][col]));
                bf[nb * 2][0] = t[0]; bf[nb * 2][1] = t[1];
                bf[nb * 2 + 1][0] = t[2]; bf[nb * 2 + 1][1] = t[3];
            }
#pragma unroll
            for (int m = 0; m < 2; m++)
#pragma unroll
                for (int n = 0; n < 8; n++)
                    mma16816(acc[m][n], ah[m], bf[n]);
        }
    }

    // ---- epilogue ----
    const float ak = WACC ? aw[kidx] : 1.f;
#pragma unroll
    for (int m = 0; m < 2; m++) {
        int rbase = rowBase + wm * 32 + m * 16 + (lane >> 2);
#pragma unroll
        for (int half = 0; half < 2; half++) {
            int rr = rbase + half * 8;
            if (rr < M) {
#pragma unroll
                for (int n = 0; n < 8; n++) {
                    int c = colBase + wn * 64 + n * 8 + (lane & 3) * 2;
                    float2 o;
                    o.x = acc[m][n][half * 2 + 0] + bias[c];
                    o.y = acc[m][n][half * 2 + 1] + bias[c + 1];
                    float2* dp = (float2*)(C + (size_t)rr * NTOT + c);
                    if (WACC) {
                        o.x *= ak; o.y *= ak;
                        if (kidx != 0) {
                            float2 old = *dp;
                            o.x += old.x; o.y += old.y;
                        }
                    }
                    *dp = o;
                }
            }
        }
    }
}

// ---------------------------------------------------------------------------
// BatchNorm statistics
// ---------------------------------------------------------------------------
__global__ void zero_stats_kernel(float* __restrict__ s, float* __restrict__ q)
{
    int i = threadIdx.x;
    s[i] = 0.f;
    q[i] = 0.f;
}

__global__ void colstats_kernel(const float* __restrict__ X, int M, int C,
                                float* __restrict__ s, float* __restrict__ q)
{
    int c = threadIdx.x;
    float ps = 0.f, pq = 0.f;
    for (int r = blockIdx.x; r < M; r += gridDim.x) {
        float v = X[(size_t)r * C + c];
        ps += v;
        pq += v * v;
    }
    atomicAdd(&s[c], ps);
    atomicAdd(&q[c], pq);
}

__global__ void finalize_kernel(const float* __restrict__ s, const float* __restrict__ q,
                                const float* __restrict__ g, const float* __restrict__ b,
                                float* __restrict__ scale, float* __restrict__ shift,
                                float invN)
{
    int c = threadIdx.x;
    float mu   = s[c] * invN;
    float var  = q[c] * invN - mu * mu;
    float rstd = rsqrtf(var + 1e-5f);
    float sc   = rstd * g[c];
    scale[c] = sc;
    shift[c] = b[c] - mu * sc;
}

__global__ void bnrelu_kernel(const float* __restrict__ X, const float* __restrict__ scale,
                              const float* __restrict__ shift, float* __restrict__ Out, int n4)
{
    int i = blockIdx.x * blockDim.x + threadIdx.x;
    if (i >= n4) return;
    int c4 = i & 31;
    float4 v  = ((const float4*)X)[i];
    float4 sc = ((const float4*)scale)[c4];
    float4 sh = ((const float4*)shift)[c4];
    v.x = fmaxf(fmaf(v.x, sc.x, sh.x), 0.f);
    v.y = fmaxf(fmaf(v.y, sc.y, sh.y), 0.f);
    v.z = fmaxf(fmaf(v.z, sc.z, sh.z), 0.f);
    v.w = fmaxf(fmaf(v.w, sc.w, sh.w), 0.f);
    ((float4*)Out)[i] = v;
}

// ---------------------------------------------------------------------------

extern "C" void kernel_launch(void* const* d_in, const int* in_sizes, int n_in,
                              void* d_out, int out_size)
{
    const int*   x     = (const int*)  d_in[0];
    const int*   ke    = (const int*)  d_in[1];
    const float* emb   = (const float*)d_in[2];
    const float* W1    = (const float*)d_in[3];
    const float* b1    = (const float*)d_in[4];
    const float* g1    = (const float*)d_in[5];
    const float* be1   = (const float*)d_in[6];
    const float* W2    = (const float*)d_in[7];
    const float* b2    = (const float*)d_in[8];
    const float* eps   = (const float*)d_in[9];
    const float* alpha = (const float*)d_in[10];
    const float* bn_g  = (const float*)d_in[11];
    const float* bn_b  = (const float*)d_in[12];

    const int N = in_sizes[0] / NFEAT;
    const int E = in_sizes[1] / (KS * 2);
    const int n4 = N * (D / 4);
    const int nTilesM = (N + BM - 1) / BM;

    float *p_h, *p_agg, *p_y1, *p_hacc, *p_sum, *p_sq, *p_scale, *p_shift, *p_aw;
    __nv_bfloat16 *p_w1h, *p_w1l, *p_w2h, *p_w2l;
    cudaGetSymbolAddress((void**)&p_h,     g_h);
    cudaGetSymbolAddress((void**)&p_agg,   g_agg);
    cudaGetSymbolAddress((void**)&p_y1,    g_y1);
    cudaGetSymbolAddress((void**)&p_hacc,  g_hacc);
    cudaGetSymbolAddress((void**)&p_sum,   g_sum);
    cudaGetSymbolAddress((void**)&p_sq,    g_sq);
    cudaGetSymbolAddress((void**)&p_scale, g_scale);
    cudaGetSymbolAddress((void**)&p_shift, g_shift);
    cudaGetSymbolAddress((void**)&p_aw,    g_aw);
    cudaGetSymbolAddress((void**)&p_w1h,   g_W1h);
    cudaGetSymbolAddress((void**)&p_w1l,   g_W1l);
    cudaGetSymbolAddress((void**)&p_w2h,   g_W2h);
    cudaGetSymbolAddress((void**)&p_w2l,   g_W2l);

    const float invN = 1.0f / (float)N;

    // split weights into hi/lo bf16 planes
    {
        int tot = 2 * LAY * D * D2;
        wsplit_kernel<<<(tot + 255) / 256, 256>>>(W1, W2, p_w1h, p_w1l, p_w2h, p_w2l);
    }

    embed_kernel<<<(N * 32 + 255) / 256, 256>>>(x, emb, p_h, N);

    for (int l = 0; l < LAY; l++) {
        softmax3_kernel<<<1, 1>>>(alpha + l * KS, p_aw);

        for (int k = 0; k < KS; k++) {
            scale_copy_kernel<<<(n4 + 255) / 256, 256>>>(p_h, p_agg, eps + l, n4);
            scatter_kernel<<<(E * 32 + 255) / 256, 256>>>(
                p_h, ke + (size_t)(k * 2) * E, ke + (size_t)(k * 2 + 1) * E, p_agg, E);

            // y1 = agg @ W1 + b1    [N,256]
            tgemm_kernel<D, D2, false, false><<<dim3(nTilesM, 2), 256>>>(
                p_agg, p_w1h + (size_t)l * D * D2, p_w1l + (size_t)l * D * D2,
                b1 + l * D2, nullptr, nullptr, nullptr, 0, p_y1, N);

            zero_stats_kernel<<<1, D2>>>(p_sum, p_sq);
            colstats_kernel<<<2048, D2>>>(p_y1, N, D2, p_sum, p_sq);
            finalize_kernel<<<1, D2>>>(p_sum, p_sq, g1 + l * D2, be1 + l * D2,
                                       p_scale, p_shift, invN);

            // hacc (+)= aw[k] * ( relu(BN(y1)) @ W2 + b2 )   [N,128]
            tgemm_kernel<D2, D, true, true><<<dim3(nTilesM, 1), 256>>>(
                p_y1, p_w2h + (size_t)l * D2 * D, p_w2l + (size_t)l * D2 * D,
                b2 + l * D, p_scale, p_shift, p_aw, k, p_hacc, N);
        }

        zero_stats_kernel<<<1, D>>>(p_sum, p_sq);
        colstats_kernel<<<2048, D>>>(p_hacc, N, D, p_sum, p_sq);
        finalize_kernel<<<1, D>>>(p_sum, p_sq, bn_g + l * D, bn_b + l * D,
                                  p_scale, p_shift, invN);

        float* outp = (l == LAY - 1) ? (float*)d_out : p_h;
        bnrelu_kernel<<<(n4 + 255) / 256, 256>>>(p_hacc, p_scale, p_shift, outp, n4);
    }
}

// round 4
// speedup vs baseline: 1.7692x; 1.0820x over previous
#include <cuda_runtime.h>
#include <cuda_bf16.h>
#include <cstdint>

// ---------------------------------------------------------------------------
// GNN_node: 3-layer relational GIN. Round 4:
//  - cp.async 2-stage pipelined split-bf16 tensor-core GEMMs (dynamic smem)
//  - k=3 relation sets batched into grid.z everywhere
//  - gemm2 accumulates into zeroed hacc via red.global.add (no k ordering)
// ---------------------------------------------------------------------------

namespace {
constexpr int D     = 128;
constexpr int D2    = 256;
constexpr int NFEAT = 9;
constexpr int VOC   = 100;
constexpr int KS    = 3;
constexpr int LAY   = 3;
constexpr int NPAD  = 100096;   // 782 * 128, covers N = 100000

constexpr int BM = 128, BN = 128, BK = 32;

// dynamic smem layout (bytes)
constexpr int OFF_ARAW = 0;                       // 2 stages * 128*32 f32 = 32768
constexpr int OFF_AH   = 32768;                   // 2 * 128*40 bf16      = 20480
constexpr int OFF_AL   = 53248;                   // 20480
constexpr int OFF_BH   = 73728;                   // 2 * 32*136 bf16      = 17408
constexpr int OFF_BL   = 91136;                   // 17408
constexpr int OFF_SC   = 108544;                  // 256 f32
constexpr int OFF_SH   = 109568;                  // 256 f32
constexpr int SMEM_BYTES = 110592;
}

// Scratch (zero-initialized at module load).
__device__ float g_h   [NPAD * D];
__device__ float g_agg [KS * NPAD * D];
__device__ float g_y1  [KS * NPAD * D2];
__device__ float g_hacc[NPAD * D];
__device__ float g_sum  [KS * D2];
__device__ float g_sq   [KS * D2];
__device__ float g_scale[KS * D2];
__device__ float g_shift[KS * D2];
__device__ float g_aw   [KS];
__device__ __align__(16) __nv_bfloat16 g_W1h[LAY * D * D2];
__device__ __align__(16) __nv_bfloat16 g_W1l[LAY * D * D2];
__device__ __align__(16) __nv_bfloat16 g_W2h[LAY * D2 * D];
__device__ __align__(16) __nv_bfloat16 g_W2l[LAY * D2 * D];

// ---------------------------------------------------------------------------
// PTX helpers
// ---------------------------------------------------------------------------
__device__ __forceinline__ void ldsm_x4(uint32_t r[4], uint32_t addr)
{
    asm volatile("ldmatrix.sync.aligned.m8n8.x4.shared.b16 {%0,%1,%2,%3}, [%4];"
                 : "=r"(r[0]), "=r"(r[1]), "=r"(r[2]), "=r"(r[3]) : "r"(addr));
}
__device__ __forceinline__ void ldsm_x4t(uint32_t r[4], uint32_t addr)
{
    asm volatile("ldmatrix.sync.aligned.m8n8.x4.trans.shared.b16 {%0,%1,%2,%3}, [%4];"
                 : "=r"(r[0]), "=r"(r[1]), "=r"(r[2]), "=r"(r[3]) : "r"(addr));
}
__device__ __forceinline__ void mma16816(float c[4], const uint32_t a[4], const uint32_t* b)
{
    asm volatile("mma.sync.aligned.m16n8k16.row.col.f32.bf16.bf16.f32 "
                 "{%0,%1,%2,%3},{%4,%5,%6,%7},{%8,%9},{%0,%1,%2,%3};"
                 : "+f"(c[0]), "+f"(c[1]), "+f"(c[2]), "+f"(c[3])
                 : "r"(a[0]), "r"(a[1]), "r"(a[2]), "r"(a[3]), "r"(b[0]), "r"(b[1]));
}
__device__ __forceinline__ uint32_t smem_u32(const void* p)
{
    return (uint32_t)__cvta_generic_to_shared(p);
}
__device__ __forceinline__ void cp16(void* smem_dst, const void* gmem_src)
{
    asm volatile("cp.async.cg.shared.global [%0], [%1], 16;"
                 :: "r"(smem_u32(smem_dst)), "l"(gmem_src) : "memory");
}

// ---------------------------------------------------------------------------
// AtomEncoder: one warp per node, float4 per lane.
// ---------------------------------------------------------------------------
__global__ void embed_kernel(const int* __restrict__ x, const float* __restrict__ emb,
                             float* __restrict__ H, int N)
{
    int gt = blockIdx.x * blockDim.x + threadIdx.x;
    int node = gt >> 5, lane = gt & 31;
    if (node >= N) return;
    float4 acc = make_float4(0.f, 0.f, 0.f, 0.f);
#pragma unroll
    for (int f = 0; f < NFEAT; f++) {
        int idx = x[node * NFEAT + f];
        float4 v = ((const float4*)(emb + ((size_t)f * VOC + idx) * D))[lane];
        acc.x += v.x; acc.y += v.y; acc.z += v.z; acc.w += v.w;
    }
    ((float4*)(H + (size_t)node * D))[lane] = acc;
}

__global__ void softmax3_kernel(const float* __restrict__ alpha, float* __restrict__ a)
{
    float a0 = alpha[0], a1 = alpha[1], a2 = alpha[2];
    float m  = fmaxf(a0, fmaxf(a1, a2));
    float e0 = expf(a0 - m), e1 = expf(a1 - m), e2 = expf(a2 - m);
    float inv = 1.f / (e0 + e1 + e2);
    a[0] = e0 * inv; a[1] = e1 * inv; a[2] = e2 * inv;
}

// split all weight matrices into hi/lo bf16 planes (once per launch)
__global__ void wsplit_kernel(const float* __restrict__ W1, const float* __restrict__ W2,
                              __nv_bfloat16* __restrict__ w1h, __nv_bfloat16* __restrict__ w1l,
                              __nv_bfloat16* __restrict__ w2h, __nv_bfloat16* __restrict__ w2l)
{
    int i = blockIdx.x * blockDim.x + threadIdx.x;
    const int tot = LAY * D * D2;
    if (i < tot) {
        float v = W1[i];
        __nv_bfloat16 h = __float2bfloat16(v);
        w1h[i] = h;
        w1l[i] = __float2bfloat16(v - __bfloat162float(h));
    } else if (i < 2 * tot) {
        int j = i - tot;
        float v = W2[j];
        __nv_bfloat16 h = __float2bfloat16(v);
        w2h[j] = h;
        w2l[j] = __float2bfloat16(v - __bfloat162float(h));
    }
}

// agg[z] = (1 + eps_l) * h   for z = 0..2 (read h once)
__global__ void scale_copy3_kernel(const float* __restrict__ H, float* __restrict__ Agg,
                                   const float* __restrict__ epsp, int n4)
{
    int i = blockIdx.x * blockDim.x + threadIdx.x;
    if (i >= n4) return;
    float s = 1.0f + epsp[0];
    float4 v = ((const float4*)H)[i];
    v.x *= s; v.y *= s; v.z *= s; v.w *= s;
    float4* a = (float4*)Agg;
    const int zs = NPAD * (D / 4);
    a[i] = v;
    a[i + zs] = v;
    a[i + 2 * zs] = v;
}

// One warp per edge, blockIdx.y = relation k.
__global__ void scatter_kernel(const float* __restrict__ H, const int* __restrict__ ke,
                               float* __restrict__ Agg, int E)
{
    int gt = blockIdx.x * blockDim.x + threadIdx.x;
    int e = gt >> 5, lane = gt & 31;
    if (e >= E) return;
    int k = blockIdx.y;
    int s = ke[(size_t)(k * 2) * E + e];
    int d = ke[(size_t)(k * 2 + 1) * E + e];
    float4 v = ((const float4*)(H + (size_t)s * D))[lane];
    float* p = Agg + (size_t)k * NPAD * D + (size_t)d * D + lane * 4;
    asm volatile("red.global.add.v4.f32 [%0], {%1, %2, %3, %4};"
                 :: "l"(p), "f"(v.x), "f"(v.y), "f"(v.z), "f"(v.w)
                 : "memory");
}

// ---------------------------------------------------------------------------
// Pipelined tensor-core split-bf16 GEMM (cp.async, 2 stages).
//   C = op(A_z)[M, KTOT] @ B + bias ;   z = blockIdx.z selects relation
//   FUSE: BN(scale_z, shift_z)+ReLU applied to A during smem conversion
//   WACC: C (+)= aw[z] * (acc + bias)  via red.global.add (C shared across z)
//   CZ:   C has per-z stride NPAD*NTOT (gemm1) vs shared (gemm2)
// ---------------------------------------------------------------------------
template <int KTOT, int NTOT, bool FUSE, bool WACC, bool CZ>
__global__ __launch_bounds__(256, 2) void tgemm_kernel(
    const float* __restrict__ A,
    const __nv_bfloat16* __restrict__ Bhp, const __nv_bfloat16* __restrict__ Blp,
    const float* __restrict__ bias,
    const float* __restrict__ scale, const float* __restrict__ shift,
    const float* __restrict__ aw,
    float* __restrict__ C, int M)
{
    extern __shared__ __align__(16) char dynsm[];
    float*         sAraw = (float*)        (dynsm + OFF_ARAW);  // [2][128][32]
    __nv_bfloat16* sAh   = (__nv_bfloat16*)(dynsm + OFF_AH);    // [2][128][40]
    __nv_bfloat16* sAl   = (__nv_bfloat16*)(dynsm + OFF_AL);
    __nv_bfloat16* sBh   = (__nv_bfloat16*)(dynsm + OFF_BH);    // [2][32][136]
    __nv_bfloat16* sBl   = (__nv_bfloat16*)(dynsm + OFF_BL);
    float*         sSc   = (float*)        (dynsm + OFF_SC);
    float*         sSh   = (float*)        (dynsm + OFF_SH);

    const int tid  = threadIdx.x;
    const int wid  = tid >> 5;
    const int lane = tid & 31;
    const int wm   = wid >> 1;
    const int wn   = wid & 1;
    const int z    = blockIdx.z;
    const int rowBase = blockIdx.x * BM;
    const int colBase = blockIdx.y * BN;

    A += (size_t)z * NPAD * KTOT;
    if (CZ) C += (size_t)z * NPAD * NTOT;
    if (FUSE) { scale += (size_t)z * KTOT; shift += (size_t)z * KTOT; }

    // copy-thread mappings
    const int ar  = tid >> 3;       // 0..31 (A rows per pass)
    const int acv = tid & 7;        // A float4 column
    const int br  = tid >> 4;       // 0..15 (B rows per pass)
    const int bcv = tid & 15;       // B 8-bf16 chunk

    auto issue_tile = [&](int t, int s) {
        const int kk = t * BK;
        float* aDst = sAraw + s * (128 * 32);
#pragma unroll
        for (int p = 0; p < 4; p++) {
            int r = ar + p * 32;
            cp16(aDst + r * 32 + acv * 4,
                 A + (size_t)(rowBase + r) * KTOT + kk + acv * 4);
        }
        __nv_bfloat16* bhDst = sBh + s * (32 * 136);
        __nv_bfloat16* blDst = sBl + s * (32 * 136);
#pragma unroll
        for (int p = 0; p < 2; p++) {
            int r = br + p * 16;
            cp16(bhDst + r * 136 + bcv * 8,
                 Bhp + (size_t)(kk + r) * NTOT + colBase + bcv * 8);
            cp16(blDst + r * 136 + bcv * 8,
                 Blp + (size_t)(kk + r) * NTOT + colBase + bcv * 8);
        }
    };

    // prologue
    issue_tile(0, 0);
    asm volatile("cp.async.commit_group;" ::: "memory");
    if (FUSE && tid < KTOT) { sSc[tid] = scale[tid]; sSh[tid] = shift[tid]; }

    float acc[2][8][4];
#pragma unroll
    for (int m = 0; m < 2; m++)
#pragma unroll
        for (int n = 0; n < 8; n++)
#pragma unroll
            for (int q = 0; q < 4; q++) acc[m][n][q] = 0.f;

    const int ktiles = KTOT / BK;
    for (int t = 0; t < ktiles; t++) {
        const int s = t & 1;
        asm volatile("cp.async.wait_group 0;" ::: "memory");
        __syncthreads();   // tile t visible to all; stage s^1 free of readers

        if (t + 1 < ktiles) {
            issue_tile(t + 1, s ^ 1);
            asm volatile("cp.async.commit_group;" ::: "memory");
        }

        // convert sAraw[s] -> split bf16 planes (optional fused BN+ReLU)
        {
            const float* aSrc = sAraw + s * (128 * 32);
            __nv_bfloat16* hDst = sAh + s * (128 * 40);
            __nv_bfloat16* lDst = sAl + s * (128 * 40);
            const int kk = t * BK;
#pragma unroll
            for (int p = 0; p < 4; p++) {
                int r = ar + p * 32;
                float4 v = *(const float4*)(aSrc + r * 32 + acv * 4);
                if (FUSE) {
                    int c = kk + acv * 4;
                    v.x = fmaxf(fmaf(v.x, sSc[c + 0], sSh[c + 0]), 0.f);
                    v.y = fmaxf(fmaf(v.y, sSc[c + 1], sSh[c + 1]), 0.f);
                    v.z = fmaxf(fmaf(v.z, sSc[c + 2], sSh[c + 2]), 0.f);
                    v.w = fmaxf(fmaf(v.w, sSc[c + 3], sSh[c + 3]), 0.f);
                }
                float vv[4] = {v.x, v.y, v.z, v.w};
#pragma unroll
                for (int j = 0; j < 4; j += 2) {
                    __nv_bfloat16 h0 = __float2bfloat16(vv[j]);
                    __nv_bfloat16 h1 = __float2bfloat16(vv[j + 1]);
                    __nv_bfloat16 l0 = __float2bfloat16(vv[j]     - __bfloat162float(h0));
                    __nv_bfloat16 l1 = __float2bfloat16(vv[j + 1] - __bfloat162float(h1));
                    __nv_bfloat162 th; th.x = h0; th.y = h1;
                    __nv_bfloat162 tl; tl.x = l0; tl.y = l1;
                    *(__nv_bfloat162*)(hDst + r * 40 + acv * 4 + j) = th;
                    *(__nv_bfloat162*)(lDst + r * 40 + acv * 4 + j) = tl;
                }
            }
        }
        __syncthreads();   // conversion visible before MMA

        // ---- MMA on stage s ----
        const __nv_bfloat16* ah_s = sAh + s * (128 * 40);
        const __nv_bfloat16* al_s = sAl + s * (128 * 40);
        const __nv_bfloat16* bh_s = sBh + s * (32 * 136);
        const __nv_bfloat16* bl_s = sBl + s * (32 * 136);
#pragma unroll
        for (int kb = 0; kb < BK / 16; kb++) {
            uint32_t ah[2][4], al[2][4], bf[8][2];
#pragma unroll
            for (int m = 0; m < 2; m++) {
                int row = wm * 32 + m * 16 + (lane & 15);
                int col = kb * 16 + (lane >> 4) * 8;
                ldsm_x4(ah[m], smem_u32(ah_s + row * 40 + col));
                ldsm_x4(al[m], smem_u32(al_s + row * 40 + col));
            }
#pragma unroll
            for (int nb = 0; nb < 4; nb++) {
                int row = kb * 16 + (lane & 15);
                int col = wn * 64 + nb * 16 + (lane >> 4) * 8;
                uint32_t tr[4];
                ldsm_x4t(tr, smem_u32(bh_s + row * 136 + col));
                bf[nb * 2][0] = tr[0]; bf[nb * 2][1] = tr[1];
                bf[nb * 2 + 1][0] = tr[2]; bf[nb * 2 + 1][1] = tr[3];
            }
#pragma unroll
            for (int m = 0; m < 2; m++)
#pragma unroll
                for (int n = 0; n < 8; n++) {
                    mma16816(acc[m][n], ah[m], bf[n]);
                    mma16816(acc[m][n], al[m], bf[n]);
                }
#pragma unroll
            for (int nb = 0; nb < 4; nb++) {
                int row = kb * 16 + (lane & 15);
                int col = wn * 64 + nb * 16 + (lane >> 4) * 8;
                uint32_t tr[4];
                ldsm_x4t(tr, smem_u32(bl_s + row * 136 + col));
                bf[nb * 2][0] = tr[0]; bf[nb * 2][1] = tr[1];
                bf[nb * 2 + 1][0] = tr[2]; bf[nb * 2 + 1][1] = tr[3];
            }
#pragma unroll
            for (int m = 0; m < 2; m++)
#pragma unroll
                for (int n = 0; n < 8; n++)
                    mma16816(acc[m][n], ah[m], bf[n]);
        }
    }

    // ---- epilogue ----
    const float ak = WACC ? aw[z] : 1.f;
#pragma unroll
    for (int m = 0; m < 2; m++) {
        int rbase = rowBase + wm * 32 + m * 16 + (lane >> 2);
#pragma unroll
        for (int half = 0; half < 2; half++) {
            int rr = rbase + half * 8;
            if (rr < M) {
#pragma unroll
                for (int n = 0; n < 8; n++) {
                    int c = colBase + wn * 64 + n * 8 + (lane & 3) * 2;
                    float2 o;
                    o.x = acc[m][n][half * 2 + 0] + bias[c];
                    o.y = acc[m][n][half * 2 + 1] + bias[c + 1];
                    float* dp = C + (size_t)rr * NTOT + c;
                    if (WACC) {
                        o.x *= ak; o.y *= ak;
                        asm volatile("red.global.add.v2.f32 [%0], {%1, %2};"
                                     :: "l"(dp), "f"(o.x), "f"(o.y) : "memory");
                    } else {
                        *(float2*)dp = o;
                    }
                }
            }
        }
    }
}

// ---------------------------------------------------------------------------
// BatchNorm statistics (blockIdx.y = relation z; zstride selects slice)
// ---------------------------------------------------------------------------
__global__ void colstats_kernel(const float* __restrict__ X, int M, int C,
                                size_t zstride,
                                float* __restrict__ s, float* __restrict__ q)
{
    int z = blockIdx.y;
    X += (size_t)z * zstride;
    s += (size_t)z * C;
    q += (size_t)z * C;
    int c = threadIdx.x;
    float ps = 0.f, pq = 0.f;
    for (int r = blockIdx.x; r < M; r += gridDim.x) {
        float v = X[(size_t)r * C + c];
        ps += v;
        pq += v * v;
    }
    atomicAdd(&s[c], ps);
    atomicAdd(&q[c], pq);
}

// blockIdx.x = relation z
__global__ void finalize_kernel(const float* __restrict__ s, const float* __restrict__ q,
                                const float* __restrict__ g, const float* __restrict__ b,
                                float* __restrict__ scale, float* __restrict__ shift,
                                float invN, int C)
{
    int k = blockIdx.x;
    int c = threadIdx.x;
    float mu   = s[k * C + c] * invN;
    float var  = q[k * C + c] * invN - mu * mu;
    float rstd = rsqrtf(var + 1e-5f);
    float sc   = rstd * g[c];
    scale[k * C + c] = sc;
    shift[k * C + c] = b[c] - mu * sc;
}

__global__ void bnrelu_kernel(const float* __restrict__ X, const float* __restrict__ scale,
                              const float* __restrict__ shift, float* __restrict__ Out, int n4)
{
    int i = blockIdx.x * blockDim.x + threadIdx.x;
    if (i >= n4) return;
    int c4 = i & 31;
    float4 v  = ((const float4*)X)[i];
    float4 sc = ((const float4*)scale)[c4];
    float4 sh = ((const float4*)shift)[c4];
    v.x = fmaxf(fmaf(v.x, sc.x, sh.x), 0.f);
    v.y = fmaxf(fmaf(v.y, sc.y, sh.y), 0.f);
    v.z = fmaxf(fmaf(v.z, sc.z, sh.z), 0.f);
    v.w = fmaxf(fmaf(v.w, sc.w, sh.w), 0.f);
    ((float4*)Out)[i] = v;
}

// ---------------------------------------------------------------------------

extern "C" void kernel_launch(void* const* d_in, const int* in_sizes, int n_in,
                              void* d_out, int out_size)
{
    const int*   x     = (const int*)  d_in[0];
    const int*   ke    = (const int*)  d_in[1];
    const float* emb   = (const float*)d_in[2];
    const float* W1    = (const float*)d_in[3];
    const float* b1    = (const float*)d_in[4];
    const float* g1    = (const float*)d_in[5];
    const float* be1   = (const float*)d_in[6];
    const float* W2    = (const float*)d_in[7];
    const float* b2    = (const float*)d_in[8];
    const float* eps   = (const float*)d_in[9];
    const float* alpha = (const float*)d_in[10];
    const float* bn_g  = (const float*)d_in[11];
    const float* bn_b  = (const float*)d_in[12];

    const int N = in_sizes[0] / NFEAT;
    const int E = in_sizes[1] / (KS * 2);
    const int n4 = N * (D / 4);
    const int nTilesM = (N + BM - 1) / BM;

    float *p_h, *p_agg, *p_y1, *p_hacc, *p_sum, *p_sq, *p_scale, *p_shift, *p_aw;
    __nv_bfloat16 *p_w1h, *p_w1l, *p_w2h, *p_w2l;
    cudaGetSymbolAddress((void**)&p_h,     g_h);
    cudaGetSymbolAddress((void**)&p_agg,   g_agg);
    cudaGetSymbolAddress((void**)&p_y1,    g_y1);
    cudaGetSymbolAddress((void**)&p_hacc,  g_hacc);
    cudaGetSymbolAddress((void**)&p_sum,   g_sum);
    cudaGetSymbolAddress((void**)&p_sq,    g_sq);
    cudaGetSymbolAddress((void**)&p_scale, g_scale);
    cudaGetSymbolAddress((void**)&p_shift, g_shift);
    cudaGetSymbolAddress((void**)&p_aw,    g_aw);
    cudaGetSymbolAddress((void**)&p_w1h,   g_W1h);
    cudaGetSymbolAddress((void**)&p_w1l,   g_W1l);
    cudaGetSymbolAddress((void**)&p_w2h,   g_W2h);
    cudaGetSymbolAddress((void**)&p_w2l,   g_W2l);

    cudaFuncSetAttribute(tgemm_kernel<D,  D2, false, false, true >,
                         cudaFuncAttributeMaxDynamicSharedMemorySize, SMEM_BYTES);
    cudaFuncSetAttribute(tgemm_kernel<D2, D,  true,  true,  false>,
                         cudaFuncAttributeMaxDynamicSharedMemorySize, SMEM_BYTES);

    const float invN = 1.0f / (float)N;

    {
        int tot = 2 * LAY * D * D2;
        wsplit_kernel<<<(tot + 255) / 256, 256>>>(W1, W2, p_w1h, p_w1l, p_w2h, p_w2l);
    }

    embed_kernel<<<(N * 32 + 255) / 256, 256>>>(x, emb, p_h, N);

    for (int l = 0; l < LAY; l++) {
        softmax3_kernel<<<1, 1>>>(alpha + l * KS, p_aw);

        // agg[z] = (1+eps)h ; scatter adds neighbors for each relation
        scale_copy3_kernel<<<(n4 + 255) / 256, 256>>>(p_h, p_agg, eps + l, n4);
        scatter_kernel<<<dim3((E * 32 + 255) / 256, KS), 256>>>(p_h, ke, p_agg, E);

        // y1[z] = agg[z] @ W1 + b1
        tgemm_kernel<D, D2, false, false, true><<<dim3(nTilesM, 2, KS), 256, SMEM_BYTES>>>(
            p_agg, p_w1h + (size_t)l * D * D2, p_w1l + (size_t)l * D * D2,
            b1 + l * D2, nullptr, nullptr, nullptr, p_y1, N);

        // per-z BN stats of y1
        cudaMemsetAsync(p_sum, 0, KS * D2 * sizeof(float));
        cudaMemsetAsync(p_sq,  0, KS * D2 * sizeof(float));
        colstats_kernel<<<dim3(1024, KS), D2>>>(p_y1, N, D2, (size_t)NPAD * D2, p_sum, p_sq);
        finalize_kernel<<<KS, D2>>>(p_sum, p_sq, g1 + l * D2, be1 + l * D2,
                                    p_scale, p_shift, invN, D2);

        // hacc = sum_z aw[z] * ( relu(BN(y1[z])) @ W2 + b2 )
        cudaMemsetAsync(p_hacc, 0, (size_t)N * D * sizeof(float));
        tgemm_kernel<D2, D, true, true, false><<<dim3(nTilesM, 1, KS), 256, SMEM_BYTES>>>(
            p_y1, p_w2h + (size_t)l * D2 * D, p_w2l + (size_t)l * D2 * D,
            b2 + l * D, p_scale, p_shift, p_aw, p_hacc, N);

        // final BN + ReLU of the layer
        cudaMemsetAsync(p_sum, 0, D * sizeof(float));
        cudaMemsetAsync(p_sq,  0, D * sizeof(float));
        colstats_kernel<<<dim3(2048, 1), D>>>(p_hacc, N, D, 0, p_sum, p_sq);
        finalize_kernel<<<1, D>>>(p_sum, p_sq, bn_g + l * D, bn_b + l * D,
                                  p_scale, p_shift, invN, D);

        float* outp = (l == LAY - 1) ? (float*)d_out : p_h;
        bnrelu_kernel<<<(n4 + 255) / 256, 256>>>(p_hacc, p_scale, p_shift, outp, n4);
    }
}

// round 5
// speedup vs baseline: 1.9244x; 1.0877x over previous
#include <cuda_runtime.h>
#include <cuda_bf16.h>
#include <cstdint>

// ---------------------------------------------------------------------------
// GNN_node: 3-layer relational GIN. Round 5:
//  - ALGEBRAIC: combine relu(BN(y1_k)) across k BEFORE gemm2 (W2 shared,
//    softmax weights sum to 1)  ->  1 gemm2 per layer instead of 3.
//  - cp.async pipelined split-bf16 tensor-core GEMMs, k batched in grid.z.
// ---------------------------------------------------------------------------

namespace {
constexpr int D     = 128;
constexpr int D2    = 256;
constexpr int NFEAT = 9;
constexpr int VOC   = 100;
constexpr int KS    = 3;
constexpr int LAY   = 3;
constexpr int NPAD  = 100096;   // 782 * 128, covers N = 100000

constexpr int BM = 128, BN = 128, BK = 32;

// dynamic smem layout (bytes)
constexpr int OFF_ARAW = 0;                       // 2 stages * 128*32 f32 = 32768
constexpr int OFF_AH   = 32768;                   // 2 * 128*40 bf16      = 20480
constexpr int OFF_AL   = 53248;                   // 20480
constexpr int OFF_BH   = 73728;                   // 2 * 32*136 bf16      = 17408
constexpr int OFF_BL   = 91136;                   // 17408
constexpr int OFF_SC   = 108544;                  // 256 f32
constexpr int OFF_SH   = 109568;                  // 256 f32
constexpr int SMEM_BYTES = 110592;
}

// Scratch (zero-initialized at module load).
__device__ float g_h   [NPAD * D];
__device__ float g_agg [KS * NPAD * D];
__device__ float g_y1  [KS * NPAD * D2];
__device__ float g_zc  [NPAD * D2];
__device__ float g_hacc[NPAD * D];
__device__ float g_sum  [KS * D2];
__device__ float g_sq   [KS * D2];
__device__ float g_scale[KS * D2];
__device__ float g_shift[KS * D2];
__device__ float g_aw   [KS];
__device__ __align__(16) __nv_bfloat16 g_W1h[LAY * D * D2];
__device__ __align__(16) __nv_bfloat16 g_W1l[LAY * D * D2];
__device__ __align__(16) __nv_bfloat16 g_W2h[LAY * D2 * D];
__device__ __align__(16) __nv_bfloat16 g_W2l[LAY * D2 * D];

// ---------------------------------------------------------------------------
// PTX helpers
// ---------------------------------------------------------------------------
__device__ __forceinline__ void ldsm_x4(uint32_t r[4], uint32_t addr)
{
    asm volatile("ldmatrix.sync.aligned.m8n8.x4.shared.b16 {%0,%1,%2,%3}, [%4];"
                 : "=r"(r[0]), "=r"(r[1]), "=r"(r[2]), "=r"(r[3]) : "r"(addr));
}
__device__ __forceinline__ void ldsm_x4t(uint32_t r[4], uint32_t addr)
{
    asm volatile("ldmatrix.sync.aligned.m8n8.x4.trans.shared.b16 {%0,%1,%2,%3}, [%4];"
                 : "=r"(r[0]), "=r"(r[1]), "=r"(r[2]), "=r"(r[3]) : "r"(addr));
}
__device__ __forceinline__ void mma16816(float c[4], const uint32_t a[4], const uint32_t* b)
{
    asm volatile("mma.sync.aligned.m16n8k16.row.col.f32.bf16.bf16.f32 "
                 "{%0,%1,%2,%3},{%4,%5,%6,%7},{%8,%9},{%0,%1,%2,%3};"
                 : "+f"(c[0]), "+f"(c[1]), "+f"(c[2]), "+f"(c[3])
                 : "r"(a[0]), "r"(a[1]), "r"(a[2]), "r"(a[3]), "r"(b[0]), "r"(b[1]));
}
__device__ __forceinline__ uint32_t smem_u32(const void* p)
{
    return (uint32_t)__cvta_generic_to_shared(p);
}
__device__ __forceinline__ void cp16(void* smem_dst, const void* gmem_src)
{
    asm volatile("cp.async.cg.shared.global [%0], [%1], 16;"
                 :: "r"(smem_u32(smem_dst)), "l"(gmem_src) : "memory");
}

// ---------------------------------------------------------------------------
// AtomEncoder: one warp per node, float4 per lane.
// ---------------------------------------------------------------------------
__global__ void embed_kernel(const int* __restrict__ x, const float* __restrict__ emb,
                             float* __restrict__ H, int N)
{
    int gt = blockIdx.x * blockDim.x + threadIdx.x;
    int node = gt >> 5, lane = gt & 31;
    if (node >= N) return;
    float4 acc = make_float4(0.f, 0.f, 0.f, 0.f);
#pragma unroll
    for (int f = 0; f < NFEAT; f++) {
        int idx = x[node * NFEAT + f];
        float4 v = ((const float4*)(emb + ((size_t)f * VOC + idx) * D))[lane];
        acc.x += v.x; acc.y += v.y; acc.z += v.z; acc.w += v.w;
    }
    ((float4*)(H + (size_t)node * D))[lane] = acc;
}

__global__ void softmax3_kernel(const float* __restrict__ alpha, float* __restrict__ a)
{
    float a0 = alpha[0], a1 = alpha[1], a2 = alpha[2];
    float m  = fmaxf(a0, fmaxf(a1, a2));
    float e0 = expf(a0 - m), e1 = expf(a1 - m), e2 = expf(a2 - m);
    float inv = 1.f / (e0 + e1 + e2);
    a[0] = e0 * inv; a[1] = e1 * inv; a[2] = e2 * inv;
}

// split all weight matrices into hi/lo bf16 planes (once per launch)
__global__ void wsplit_kernel(const float* __restrict__ W1, const float* __restrict__ W2,
                              __nv_bfloat16* __restrict__ w1h, __nv_bfloat16* __restrict__ w1l,
                              __nv_bfloat16* __restrict__ w2h, __nv_bfloat16* __restrict__ w2l)
{
    int i = blockIdx.x * blockDim.x + threadIdx.x;
    const int tot = LAY * D * D2;
    if (i < tot) {
        float v = W1[i];
        __nv_bfloat16 h = __float2bfloat16(v);
        w1h[i] = h;
        w1l[i] = __float2bfloat16(v - __bfloat162float(h));
    } else if (i < 2 * tot) {
        int j = i - tot;
        float v = W2[j];
        __nv_bfloat16 h = __float2bfloat16(v);
        w2h[j] = h;
        w2l[j] = __float2bfloat16(v - __bfloat162float(h));
    }
}

// agg[z] = (1 + eps_l) * h   for z = 0..2 (read h once)
__global__ void scale_copy3_kernel(const float* __restrict__ H, float* __restrict__ Agg,
                                   const float* __restrict__ epsp, int n4)
{
    int i = blockIdx.x * blockDim.x + threadIdx.x;
    if (i >= n4) return;
    float s = 1.0f + epsp[0];
    float4 v = ((const float4*)H)[i];
    v.x *= s; v.y *= s; v.z *= s; v.w *= s;
    float4* a = (float4*)Agg;
    const int zs = NPAD * (D / 4);
    a[i] = v;
    a[i + zs] = v;
    a[i + 2 * zs] = v;
}

// One warp per edge, blockIdx.y = relation k.
__global__ void scatter_kernel(const float* __restrict__ H, const int* __restrict__ ke,
                               float* __restrict__ Agg, int E)
{
    int gt = blockIdx.x * blockDim.x + threadIdx.x;
    int e = gt >> 5, lane = gt & 31;
    if (e >= E) return;
    int k = blockIdx.y;
    int s = ke[(size_t)(k * 2) * E + e];
    int d = ke[(size_t)(k * 2 + 1) * E + e];
    float4 v = ((const float4*)(H + (size_t)s * D))[lane];
    float* p = Agg + (size_t)k * NPAD * D + (size_t)d * D + lane * 4;
    asm volatile("red.global.add.v4.f32 [%0], {%1, %2, %3, %4};"
                 :: "l"(p), "f"(v.x), "f"(v.y), "f"(v.z), "f"(v.w)
                 : "memory");
}

// ---------------------------------------------------------------------------
// Pipelined tensor-core split-bf16 GEMM (cp.async, 2 stages).
//   C = A_z[M, KTOT] @ B + bias ;   z = blockIdx.z
//   CZ: per-z strides on A and C (gemm1). gemm2 runs with z=0 only.
// ---------------------------------------------------------------------------
template <int KTOT, int NTOT, bool CZ>
__global__ __launch_bounds__(256, 2) void tgemm_kernel(
    const float* __restrict__ A,
    const __nv_bfloat16* __restrict__ Bhp, const __nv_bfloat16* __restrict__ Blp,
    const float* __restrict__ bias,
    float* __restrict__ C, int M)
{
    extern __shared__ __align__(16) char dynsm[];
    float*         sAraw = (float*)        (dynsm + OFF_ARAW);
    __nv_bfloat16* sAh   = (__nv_bfloat16*)(dynsm + OFF_AH);
    __nv_bfloat16* sAl   = (__nv_bfloat16*)(dynsm + OFF_AL);
    __nv_bfloat16* sBh   = (__nv_bfloat16*)(dynsm + OFF_BH);
    __nv_bfloat16* sBl   = (__nv_bfloat16*)(dynsm + OFF_BL);

    const int tid  = threadIdx.x;
    const int wid  = tid >> 5;
    const int lane = tid & 31;
    const int wm   = wid >> 1;
    const int wn   = wid & 1;
    const int rowBase = blockIdx.x * BM;
    const int colBase = blockIdx.y * BN;

    if (CZ) {
        const int z = blockIdx.z;
        A += (size_t)z * NPAD * KTOT;
        C += (size_t)z * NPAD * NTOT;
    }

    const int ar  = tid >> 3;
    const int acv = tid & 7;
    const int br  = tid >> 4;
    const int bcv = tid & 15;

    auto issue_tile = [&](int t, int s) {
        const int kk = t * BK;
        float* aDst = sAraw + s * (128 * 32);
#pragma unroll
        for (int p = 0; p < 4; p++) {
            int r = ar + p * 32;
            cp16(aDst + r * 32 + acv * 4,
                 A + (size_t)(rowBase + r) * KTOT + kk + acv * 4);
        }
        __nv_bfloat16* bhDst = sBh + s * (32 * 136);
        __nv_bfloat16* blDst = sBl + s * (32 * 136);
#pragma unroll
        for (int p = 0; p < 2; p++) {
            int r = br + p * 16;
            cp16(bhDst + r * 136 + bcv * 8,
                 Bhp + (size_t)(kk + r) * NTOT + colBase + bcv * 8);
            cp16(blDst + r * 136 + bcv * 8,
                 Blp + (size_t)(kk + r) * NTOT + colBase + bcv * 8);
        }
    };

    issue_tile(0, 0);
    asm volatile("cp.async.commit_group;" ::: "memory");

    float acc[2][8][4];
#pragma unroll
    for (int m = 0; m < 2; m++)
#pragma unroll
        for (int n = 0; n < 8; n++)
#pragma unroll
            for (int q = 0; q < 4; q++) acc[m][n][q] = 0.f;

    const int ktiles = KTOT / BK;
    for (int t = 0; t < ktiles; t++) {
        const int s = t & 1;
        asm volatile("cp.async.wait_group 0;" ::: "memory");
        __syncthreads();

        if (t + 1 < ktiles) {
            issue_tile(t + 1, s ^ 1);
            asm volatile("cp.async.commit_group;" ::: "memory");
        }

        // convert fp32 stage -> split bf16 planes
        {
            const float* aSrc = sAraw + s * (128 * 32);
            __nv_bfloat16* hDst = sAh + s * (128 * 40);
            __nv_bfloat16* lDst = sAl + s * (128 * 40);
#pragma unroll
            for (int p = 0; p < 4; p++) {
                int r = ar + p * 32;
                float4 v = *(const float4*)(aSrc + r * 32 + acv * 4);
                float vv[4] = {v.x, v.y, v.z, v.w};
#pragma unroll
                for (int j = 0; j < 4; j += 2) {
                    __nv_bfloat16 h0 = __float2bfloat16(vv[j]);
                    __nv_bfloat16 h1 = __float2bfloat16(vv[j + 1]);
                    __nv_bfloat16 l0 = __float2bfloat16(vv[j]     - __bfloat162float(h0));
                    __nv_bfloat16 l1 = __float2bfloat16(vv[j + 1] - __bfloat162float(h1));
                    __nv_bfloat162 th; th.x = h0; th.y = h1;
                    __nv_bfloat162 tl; tl.x = l0; tl.y = l1;
                    *(__nv_bfloat162*)(hDst + r * 40 + acv * 4 + j) = th;
                    *(__nv_bfloat162*)(lDst + r * 40 + acv * 4 + j) = tl;
                }
            }
        }
        __syncthreads();

        const __nv_bfloat16* ah_s = sAh + s * (128 * 40);
        const __nv_bfloat16* al_s = sAl + s * (128 * 40);
        const __nv_bfloat16* bh_s = sBh + s * (32 * 136);
        const __nv_bfloat16* bl_s = sBl + s * (32 * 136);
#pragma unroll
        for (int kb = 0; kb < BK / 16; kb++) {
            uint32_t ah[2][4], al[2][4], bf[8][2];
#pragma unroll
            for (int m = 0; m < 2; m++) {
                int row = wm * 32 + m * 16 + (lane & 15);
                int col = kb * 16 + (lane >> 4) * 8;
                ldsm_x4(ah[m], smem_u32(ah_s + row * 40 + col));
                ldsm_x4(al[m], smem_u32(al_s + row * 40 + col));
            }
#pragma unroll
            for (int nb = 0; nb < 4; nb++) {
                int row = kb * 16 + (lane & 15);
                int col = wn * 64 + nb * 16 + (lane >> 4) * 8;
                uint32_t tr[4];
                ldsm_x4t(tr, smem_u32(bh_s + row * 136 + col));
                bf[nb * 2][0] = tr[0]; bf[nb * 2][1] = tr[1];
                bf[nb * 2 + 1][0] = tr[2]; bf[nb * 2 + 1][1] = tr[3];
            }
#pragma unroll
            for (int m = 0; m < 2; m++)
#pragma unroll
                for (int n = 0; n < 8; n++) {
                    mma16816(acc[m][n], ah[m], bf[n]);
                    mma16816(acc[m][n], al[m], bf[n]);
                }
#pragma unroll
            for (int nb = 0; nb < 4; nb++) {
                int row = kb * 16 + (lane & 15);
                int col = wn * 64 + nb * 16 + (lane >> 4) * 8;
                uint32_t tr[4];
                ldsm_x4t(tr, smem_u32(bl_s + row * 136 + col));
                bf[nb * 2][0] = tr[0]; bf[nb * 2][1] = tr[1];
                bf[nb * 2 + 1][0] = tr[2]; bf[nb * 2 + 1][1] = tr[3];
            }
#pragma unroll
            for (int m = 0; m < 2; m++)
#pragma unroll
                for (int n = 0; n < 8; n++)
                    mma16816(acc[m][n], ah[m], bf[n]);
        }
    }

    // ---- epilogue: plain stores ----
#pragma unroll
    for (int m = 0; m < 2; m++) {
        int rbase = rowBase + wm * 32 + m * 16 + (lane >> 2);
#pragma unroll
        for (int half = 0; half < 2; half++) {
            int rr = rbase + half * 8;
            if (rr < M) {
#pragma unroll
                for (int n = 0; n < 8; n++) {
                    int c = colBase + wn * 64 + n * 8 + (lane & 3) * 2;
                    float2 o;
                    o.x = acc[m][n][half * 2 + 0] + bias[c];
                    o.y = acc[m][n][half * 2 + 1] + bias[c + 1];
                    *(float2*)(C + (size_t)rr * NTOT + c) = o;
                }
            }
        }
    }
}

// ---------------------------------------------------------------------------
// zc = sum_k aw[k] * relu( y1_k * scale_k + shift_k )      [N, 256]
// ---------------------------------------------------------------------------
__global__ void combine_kernel(const float* __restrict__ Y1,
                               const float* __restrict__ scale,
                               const float* __restrict__ shift,
                               const float* __restrict__ aw,
                               float* __restrict__ Zc, int n4)
{
    int i = blockIdx.x * blockDim.x + threadIdx.x;
    if (i >= n4) return;
    int c4 = i & 63;   // 256 floats per row = 64 float4
    float4 acc = make_float4(0.f, 0.f, 0.f, 0.f);
    const int zs = NPAD * (D2 / 4);
#pragma unroll
    for (int k = 0; k < KS; k++) {
        float a = __ldg(aw + k);
        float4 v  = __ldg((const float4*)Y1 + (size_t)k * zs + i);
        float4 sc = __ldg((const float4*)(scale + k * D2) + c4);
        float4 sh = __ldg((const float4*)(shift + k * D2) + c4);
        acc.x += a * fmaxf(fmaf(v.x, sc.x, sh.x), 0.f);
        acc.y += a * fmaxf(fmaf(v.y, sc.y, sh.y), 0.f);
        acc.z += a * fmaxf(fmaf(v.z, sc.z, sh.z), 0.f);
        acc.w += a * fmaxf(fmaf(v.w, sc.w, sh.w), 0.f);
    }
    ((float4*)Zc)[i] = acc;
}

// ---------------------------------------------------------------------------
// BatchNorm statistics (blockIdx.y = relation z; zstride selects slice)
// ---------------------------------------------------------------------------
__global__ void colstats_kernel(const float* __restrict__ X, int M, int C,
                                size_t zstride,
                                float* __restrict__ s, float* __restrict__ q)
{
    int z = blockIdx.y;
    X += (size_t)z * zstride;
    s += (size_t)z * C;
    q += (size_t)z * C;
    int c = threadIdx.x;
    float ps = 0.f, pq = 0.f;
    for (int r = blockIdx.x; r < M; r += gridDim.x) {
        float v = X[(size_t)r * C + c];
        ps += v;
        pq += v * v;
    }
    atomicAdd(&s[c], ps);
    atomicAdd(&q[c], pq);
}

__global__ void finalize_kernel(const float* __restrict__ s, const float* __restrict__ q,
                                const float* __restrict__ g, const float* __restrict__ b,
                                float* __restrict__ scale, float* __restrict__ shift,
                                float invN, int C)
{
    int k = blockIdx.x;
    int c = threadIdx.x;
    float mu   = s[k * C + c] * invN;
    float var  = q[k * C + c] * invN - mu * mu;
    float rstd = rsqrtf(var + 1e-5f);
    float sc   = rstd * g[c];
    scale[k * C + c] = sc;
    shift[k * C + c] = b[c] - mu * sc;
}

__global__ void bnrelu_kernel(const float* __restrict__ X, const float* __restrict__ scale,
                              const float* __restrict__ shift, float* __restrict__ Out, int n4)
{
    int i = blockIdx.x * blockDim.x + threadIdx.x;
    if (i >= n4) return;
    int c4 = i & 31;
    float4 v  = ((const float4*)X)[i];
    float4 sc = ((const float4*)scale)[c4];
    float4 sh = ((const float4*)shift)[c4];
    v.x = fmaxf(fmaf(v.x, sc.x, sh.x), 0.f);
    v.y = fmaxf(fmaf(v.y, sc.y, sh.y), 0.f);
    v.z = fmaxf(fmaf(v.z, sc.z, sh.z), 0.f);
    v.w = fmaxf(fmaf(v.w, sc.w, sh.w), 0.f);
    ((float4*)Out)[i] = v;
}

// ---------------------------------------------------------------------------

extern "C" void kernel_launch(void* const* d_in, const int* in_sizes, int n_in,
                              void* d_out, int out_size)
{
    const int*   x     = (const int*)  d_in[0];
    const int*   ke    = (const int*)  d_in[1];
    const float* emb   = (const float*)d_in[2];
    const float* W1    = (const float*)d_in[3];
    const float* b1    = (const float*)d_in[4];
    const float* g1    = (const float*)d_in[5];
    const float* be1   = (const float*)d_in[6];
    const float* W2    = (const float*)d_in[7];
    const float* b2    = (const float*)d_in[8];
    const float* eps   = (const float*)d_in[9];
    const float* alpha = (const float*)d_in[10];
    const float* bn_g  = (const float*)d_in[11];
    const float* bn_b  = (const float*)d_in[12];

    const int N = in_sizes[0] / NFEAT;
    const int E = in_sizes[1] / (KS * 2);
    const int n4  = N * (D / 4);
    const int n4b = N * (D2 / 4);
    const int nTilesM = (N + BM - 1) / BM;

    float *p_h, *p_agg, *p_y1, *p_zc, *p_hacc, *p_sum, *p_sq, *p_scale, *p_shift, *p_aw;
    __nv_bfloat16 *p_w1h, *p_w1l, *p_w2h, *p_w2l;
    cudaGetSymbolAddress((void**)&p_h,     g_h);
    cudaGetSymbolAddress((void**)&p_agg,   g_agg);
    cudaGetSymbolAddress((void**)&p_y1,    g_y1);
    cudaGetSymbolAddress((void**)&p_zc,    g_zc);
    cudaGetSymbolAddress((void**)&p_hacc,  g_hacc);
    cudaGetSymbolAddress((void**)&p_sum,   g_sum);
    cudaGetSymbolAddress((void**)&p_sq,    g_sq);
    cudaGetSymbolAddress((void**)&p_scale, g_scale);
    cudaGetSymbolAddress((void**)&p_shift, g_shift);
    cudaGetSymbolAddress((void**)&p_aw,    g_aw);
    cudaGetSymbolAddress((void**)&p_w1h,   g_W1h);
    cudaGetSymbolAddress((void**)&p_w1l,   g_W1l);
    cudaGetSymbolAddress((void**)&p_w2h,   g_W2h);
    cudaGetSymbolAddress((void**)&p_w2l,   g_W2l);

    cudaFuncSetAttribute(tgemm_kernel<D,  D2, true >,
                         cudaFuncAttributeMaxDynamicSharedMemorySize, SMEM_BYTES);
    cudaFuncSetAttribute(tgemm_kernel<D2, D,  false>,
                         cudaFuncAttributeMaxDynamicSharedMemorySize, SMEM_BYTES);

    const float invN = 1.0f / (float)N;

    {
        int tot = 2 * LAY * D * D2;
        wsplit_kernel<<<(tot + 255) / 256, 256>>>(W1, W2, p_w1h, p_w1l, p_w2h, p_w2l);
    }

    embed_kernel<<<(N * 32 + 255) / 256, 256>>>(x, emb, p_h, N);

    for (int l = 0; l < LAY; l++) {
        softmax3_kernel<<<1, 1>>>(alpha + l * KS, p_aw);

        // agg[z] = (1+eps)h ; scatter adds neighbors per relation
        scale_copy3_kernel<<<(n4 + 255) / 256, 256>>>(p_h, p_agg, eps + l, n4);
        scatter_kernel<<<dim3((E * 32 + 255) / 256, KS), 256>>>(p_h, ke, p_agg, E);

        // y1[z] = agg[z] @ W1 + b1
        tgemm_kernel<D, D2, true><<<dim3(nTilesM, 2, KS), 256, SMEM_BYTES>>>(
            p_agg, p_w1h + (size_t)l * D * D2, p_w1l + (size_t)l * D * D2,
            b1 + l * D2, p_y1, N);

        // per-z BN stats of y1
        cudaMemsetAsync(p_sum, 0, KS * D2 * sizeof(float));
        cudaMemsetAsync(p_sq,  0, KS * D2 * sizeof(float));
        colstats_kernel<<<dim3(1024, KS), D2>>>(p_y1, N, D2, (size_t)NPAD * D2, p_sum, p_sq);
        finalize_kernel<<<KS, D2>>>(p_sum, p_sq, g1 + l * D2, be1 + l * D2,
                                    p_scale, p_shift, invN, D2);

        // zc = sum_k aw[k] * relu(BN_k(y1_k))   (W2 shared -> single gemm2)
        combine_kernel<<<(n4b + 255) / 256, 256>>>(p_y1, p_scale, p_shift, p_aw, p_zc, n4b);

        // hacc = zc @ W2 + b2
        tgemm_kernel<D2, D, false><<<dim3(nTilesM, 1, 1), 256, SMEM_BYTES>>>(
            p_zc, p_w2h + (size_t)l * D2 * D, p_w2l + (size_t)l * D2 * D,
            b2 + l * D, p_hacc, N);

        // final BN + ReLU of the layer
        cudaMemsetAsync(p_sum, 0, D * sizeof(float));
        cudaMemsetAsync(p_sq,  0, D * sizeof(float));
        colstats_kernel<<<dim3(2048, 1), D>>>(p_hacc, N, D, 0, p_sum, p_sq);
        finalize_kernel<<<1, D>>>(p_sum, p_sq, bn_g + l * D, bn_b + l * D,
                                  p_scale, p_shift, invN, D);

        float* outp = (l == LAY - 1) ? (float*)d_out : p_h;
        bnrelu_kernel<<<(n4 + 255) / 256, 256>>>(p_hacc, p_scale, p_shift, outp, n4);
    }
}